// round 7
// baseline (speedup 1.0000x reference)
#include <cuda_runtime.h>
#include <cuda_fp16.h>
#include <math.h>
#include <cstdint>

#define NN 16384
#define CC 256
#define HH 8
#define HD 512
#define QKVW 1536
#define HIDD 512
#define OUTD 64
#define H2D 532
#define ATTKP 576   // 520 padded to 64-multiple
#define H2KP 576    // 532 padded

// ---------------- scratch (static device arrays; no allocation) ----------------
__device__ float g_QKV[NN * QKVW];          // fp32 Q|K|V for attention
__device__ float g_G[NN * HH];
__device__ float g_Z[NN * OUTD];
__device__ float g_part[NN];                // per-node vq loss partials

// activation fp16 limbs (zero-init pads stay zero forever)
__device__ __half g_xl0[NN * CC], g_xl1[NN * CC];
__device__ __half g_Al0[NN * ATTKP], g_Al1[NN * ATTKP];
__device__ __half g_Tl0[NN * CC], g_Tl1[NN * CC];
__device__ __half g_Hl0[NN * H2KP], g_Hl1[NN * H2KP];

// weight fp16 limbs, [N, Kp] K-major
__device__ __half g_Bq0[QKVW * CC], g_Bq1[QKVW * CC];
__device__ __half g_Bo0[CC * ATTKP], g_Bo1[CC * ATTKP];
__device__ __half g_Bl0[HIDD * CC], g_Bl1[HIDD * CC];
__device__ __half g_Bu0[OUTD * H2KP], g_Bu1[OUTD * H2KP];

// ---------------- helpers ----------------
__device__ __forceinline__ float gelu_tanh(float x) {
    float x3 = x * x * x;
    return 0.5f * x * (1.0f + tanhf(0.7978845608028654f * (x + 0.044715f * x3)));
}

__device__ __forceinline__ void store2(__half* p0, __half* p1, size_t off, float v) {
    __half h0 = __float2half_rn(v);
    __half h1 = __float2half_rn(v - __half2float(h0));
    p0[off] = h0;
    p1[off] = h1;
}

__device__ __forceinline__ uint32_t smem_u32(const void* p) {
    uint32_t a;
    asm("{ .reg .u64 t; cvta.to.shared.u64 t, %1; cvt.u32.u64 %0, t; }" : "=r"(a) : "l"(p));
    return a;
}

__device__ __forceinline__ void ldsm4(uint32_t* r, uint32_t addr) {
    asm volatile("ldmatrix.sync.aligned.m8n8.x4.shared.b16 {%0,%1,%2,%3}, [%4];"
                 : "=r"(r[0]), "=r"(r[1]), "=r"(r[2]), "=r"(r[3]) : "r"(addr));
}

__device__ __forceinline__ void mma16816(float* c, const uint32_t* a, const uint32_t* b) {
    asm volatile(
        "mma.sync.aligned.m16n8k16.row.col.f32.f16.f16.f32 "
        "{%0,%1,%2,%3}, {%4,%5,%6,%7}, {%8,%9}, {%0,%1,%2,%3};"
        : "+f"(c[0]), "+f"(c[1]), "+f"(c[2]), "+f"(c[3])
        : "r"(a[0]), "r"(a[1]), "r"(a[2]), "r"(a[3]), "r"(b[0]), "r"(b[1]));
}

// ============== mma.sync fp16 2-limb 3-pass GEMM: C = A*B^T ==============
// Tiles loaded once per chunk (A0,A1,B0,B1), 3 limb passes from shared.
// EPI: 0=fp32 plain, 1=resid+dyntanh->limbs, 2=gelu(bias)+dyntanh->limbs,
//      3=tanh(gelu(bias))->fp32
template <int NT, int EPI>
__global__ __launch_bounds__(256) void mmagemm(
        const __half* __restrict__ A0, const __half* __restrict__ A1,
        const __half* __restrict__ B0, const __half* __restrict__ B1,
        int Kp,
        float* __restrict__ outF, int ldoF,
        __half* __restrict__ O0, __half* __restrict__ O1, int ldoL,
        const float* __restrict__ bias, const float* __restrict__ resid, int ldr,
        const float* __restrict__ alpha_p,
        const float* __restrict__ gv, const float* __restrict__ bv) {
    extern __shared__ __half sm[];
    __half(*As0)[72] = (__half(*)[72])sm;
    __half(*As1)[72] = (__half(*)[72])(sm + 128 * 72);
    __half(*Bs0)[72] = (__half(*)[72])(sm + 2 * 128 * 72);
    __half(*Bs1)[72] = (__half(*)[72])(sm + 2 * 128 * 72 + NT * 72);
    constexpr int NF = NT / 32;   // n-frags per warp (8 cols each)

    int tid = threadIdx.x, lane = tid & 31, wid = tid >> 5;
    int wm = wid & 1, wn = wid >> 1;
    int bm = blockIdx.y * 128, bn = blockIdx.x * NT;
    int nch = Kp >> 6;

    float acc[4][NF][4];
#pragma unroll
    for (int i = 0; i < 4; i++)
#pragma unroll
        for (int j = 0; j < NF; j++)
#pragma unroll
            for (int c = 0; c < 4; c++) acc[i][j][c] = 0.f;

#pragma unroll 1
    for (int c = 0; c < nch; c++) {
        __syncthreads();   // previous chunk's compute done
        // load A limb tiles [128 x 64]
#pragma unroll
        for (int q = 0; q < 4; q++) {
            int idx = tid + q * 256;
            int row = idx >> 3, cg = idx & 7;
            size_t go = (size_t)(bm + row) * Kp + c * 64 + cg * 8;
            *(uint4*)&As0[row][cg * 8] = *(const uint4*)(A0 + go);
            *(uint4*)&As1[row][cg * 8] = *(const uint4*)(A1 + go);
        }
        // load B limb tiles [NT x 64]
#pragma unroll
        for (int q = 0; q < NF; q++) {
            int idx = tid + q * 256;
            int row = idx >> 3, cg = idx & 7;
            size_t go = (size_t)(bn + row) * Kp + c * 64 + cg * 8;
            *(uint4*)&Bs0[row][cg * 8] = *(const uint4*)(B0 + go);
            *(uint4*)&Bs1[row][cg * 8] = *(const uint4*)(B1 + go);
        }
        __syncthreads();

#pragma unroll
        for (int kk = 0; kk < 4; kk++) {
            int k = kk * 16;
            int arow = wm * 64 + (lane & 15);
            int acol = k + (lane >> 4) * 8;
            int g = lane >> 3;
            int nr = wn * (NT / 4) + ((g >> 1) << 3) + (lane & 7);
            int kc = k + (g & 1) * 8;

            uint32_t a0[4][4], b0[NF][2];
#pragma unroll
            for (int i = 0; i < 4; i++) ldsm4(a0[i], smem_u32(&As0[arow + i * 16][acol]));
#pragma unroll
            for (int jj = 0; jj < NF / 2; jj++) {
                uint32_t tmp[4];
                ldsm4(tmp, smem_u32(&Bs0[nr + jj * 16][kc]));
                b0[2 * jj][0] = tmp[0]; b0[2 * jj][1] = tmp[1];
                b0[2 * jj + 1][0] = tmp[2]; b0[2 * jj + 1][1] = tmp[3];
            }
#pragma unroll
            for (int i = 0; i < 4; i++)
#pragma unroll
                for (int j = 0; j < NF; j++) mma16816(acc[i][j], a0[i], b0[j]);

            uint32_t b1[NF][2];
#pragma unroll
            for (int jj = 0; jj < NF / 2; jj++) {
                uint32_t tmp[4];
                ldsm4(tmp, smem_u32(&Bs1[nr + jj * 16][kc]));
                b1[2 * jj][0] = tmp[0]; b1[2 * jj][1] = tmp[1];
                b1[2 * jj + 1][0] = tmp[2]; b1[2 * jj + 1][1] = tmp[3];
            }
#pragma unroll
            for (int i = 0; i < 4; i++)
#pragma unroll
                for (int j = 0; j < NF; j++) mma16816(acc[i][j], a0[i], b1[j]);

            uint32_t a1[4][4];
#pragma unroll
            for (int i = 0; i < 4; i++) ldsm4(a1[i], smem_u32(&As1[arow + i * 16][acol]));
#pragma unroll
            for (int i = 0; i < 4; i++)
#pragma unroll
                for (int j = 0; j < NF; j++) mma16816(acc[i][j], a1[i], b0[j]);
        }
    }

    // ---------------- epilogue ----------------
    float alpha = (EPI == 1 || EPI == 2) ? *alpha_p : 0.f;
    int gid = lane >> 2, tig = lane & 3;
#pragma unroll
    for (int i = 0; i < 4; i++) {
#pragma unroll
        for (int j = 0; j < NF; j++) {
#pragma unroll
            for (int cc = 0; cc < 4; cc++) {
                int m = bm + wm * 64 + i * 16 + gid + (cc >> 1) * 8;
                int ncol = bn + wn * (NT / 4) + j * 8 + tig * 2 + (cc & 1);
                float v = acc[i][j][cc];
                if (EPI == 0) {
                    outF[(size_t)m * ldoF + ncol] = v;
                } else if (EPI == 1) {
                    v += resid[(size_t)m * ldr + ncol];
                    v = tanhf(alpha * v) * gv[ncol] + bv[ncol];
                    store2(O0, O1, (size_t)m * ldoL + ncol, v);
                } else if (EPI == 2) {
                    v = gelu_tanh(v + bias[ncol]);
                    v = tanhf(alpha * v) * gv[ncol] + bv[ncol];
                    store2(O0, O1, (size_t)m * ldoL + ncol, v);
                } else {
                    v = tanhf(gelu_tanh(v + bias[ncol]));
                    outF[(size_t)m * ldoF + ncol] = v;
                }
            }
        }
    }
}

// ---------------- conversions ----------------
__global__ void convA_kernel(const float* __restrict__ src, __half* d0, __half* d1, int n) {
    int t = blockIdx.x * blockDim.x + threadIdx.x;
    if (t >= n) return;
    store2(d0, d1, t, src[t]);
}

__global__ void convB_kernel(const float* __restrict__ src, __half* d0, __half* d1,
                             int K, int N, int Kp) {
    int t = blockIdx.x * blockDim.x + threadIdx.x;
    if (t >= N * K) return;
    int n = t / K, k = t - n * K;
    store2(d0, d1, (size_t)n * Kp + k, src[(size_t)k * N + n]);
}

__global__ void convBqkv_kernel(const float* __restrict__ Wq, const float* __restrict__ Wk,
                                const float* __restrict__ Wv, __half* d0, __half* d1) {
    int t = blockIdx.x * blockDim.x + threadIdx.x;
    if (t >= QKVW * CC) return;
    int n = t >> 8, k = t & 255;
    const float* s = (n < 512) ? Wq : ((n < 1024) ? Wk : Wv);
    int col = n & 511;
    store2(d0, d1, (size_t)n * CC + k, s[(size_t)k * 512 + col]);
}

// ---------------- gate projection: warp per node ----------------
__global__ void gate_kernel(const float* __restrict__ x, const float* __restrict__ wg) {
    int wid = threadIdx.x >> 5, lane = threadIdx.x & 31;
    int n = blockIdx.x * 8 + wid;
    if (n >= NN) return;
    const float* xr = x + (size_t)n * CC;
    float4 v0 = *(const float4*)(xr + lane * 8);
    float4 v1 = *(const float4*)(xr + lane * 8 + 4);
    float xv[8] = {v0.x, v0.y, v0.z, v0.w, v1.x, v1.y, v1.z, v1.w};
#pragma unroll
    for (int h = 0; h < 8; h++) {
        float p = 0.f;
#pragma unroll
        for (int i = 0; i < 8; i++) p = fmaf(xv[i], wg[(lane * 8 + i) * 8 + h], p);
#pragma unroll
        for (int o = 16; o; o >>= 1) p += __shfl_xor_sync(0xffffffffu, p, o);
        if (lane == 0) g_G[(size_t)n * 8 + h] = p;
    }
}

// ---------------- attention: block per node, warp per head; writes Att limbs ------
__global__ void attn_kernel(const float* __restrict__ coors, const int* __restrict__ nbr,
                            const float* __restrict__ Wr1, const float* __restrict__ br1,
                            const float* __restrict__ Wr2, const float* __restrict__ br2) {
    int n = blockIdx.x;
    int tid = threadIdx.x;
    __shared__ int s_nbr[8];
    __shared__ float s_dist[8];
    __shared__ float s_unit[8][3];
    __shared__ float s_rad[8][8];
    __shared__ float s_gate[8][8];

    if (tid < 8) s_nbr[tid] = nbr[(size_t)n * 8 + tid];
    __syncthreads();
    if (tid < 8) {
        int j = tid;
        float cx = coors[(size_t)n * 3], cy = coors[(size_t)n * 3 + 1], cz = coors[(size_t)n * 3 + 2];
        int mm = s_nbr[j];
        float rx = coors[(size_t)mm * 3] - cx;
        float ry = coors[(size_t)mm * 3 + 1] - cy;
        float rz = coors[(size_t)mm * 3 + 2] - cz;
        float d = sqrtf(rx * rx + ry * ry + rz * rz + 1e-8f);
        s_dist[j] = d;
        s_unit[j][0] = rx / d;
        s_unit[j][1] = ry / d;
        s_unit[j][2] = rz / d;
    }
    __syncthreads();
    if (tid < 64) {
        int j = tid >> 3, h = tid & 7;
        float d = s_dist[j];
        float acc = br2[h];
#pragma unroll
        for (int i = 0; i < 16; i++)
            acc = fmaf(gelu_tanh(d * Wr1[i] + br1[i]), Wr2[i * 8 + h], acc);
        s_rad[j][h] = acc;
        s_gate[j][h] = g_G[(size_t)s_nbr[j] * HH + h];
    }
    __syncthreads();

    int w = tid >> 5, lane = tid & 31;
    int h = w;
    const float* qr = g_QKV + (size_t)n * QKVW + h * 64;
    float q0 = qr[lane * 2], q1 = qr[lane * 2 + 1];
    float logit[8];
#pragma unroll
    for (int j = 0; j < 8; j++) {
        const float* kr = g_QKV + (size_t)s_nbr[j] * QKVW + 512 + h * 64;
        float p = q0 * kr[lane * 2] + q1 * kr[lane * 2 + 1];
#pragma unroll
        for (int o = 16; o; o >>= 1) p += __shfl_xor_sync(0xffffffffu, p, o);
        p = p * 0.125f + s_rad[j][h];
        logit[j] = (s_dist[j] <= 10.0f) ? p : -1e9f;
    }
    float mx = logit[0];
#pragma unroll
    for (int j = 1; j < 8; j++) mx = fmaxf(mx, logit[j]);
    float e[8];
    float se = 0.f;
#pragma unroll
    for (int j = 0; j < 8; j++) { e[j] = expf(logit[j] - mx); se += e[j]; }
    float inv = 1.f / se;
    float a0 = 0.f, a1 = 0.f;
#pragma unroll
    for (int j = 0; j < 8; j++) {
        float at = e[j] * inv;
        const float* vr = g_QKV + (size_t)s_nbr[j] * QKVW + 1024 + h * 64;
        a0 = fmaf(at, vr[lane * 2], a0);
        a1 = fmaf(at, vr[lane * 2 + 1], a1);
    }
    size_t base = (size_t)n * ATTKP + h * 64 + lane * 2;
    store2(g_Al0, g_Al1, base, a0);
    store2(g_Al0, g_Al1, base + 1, a1);
    if (lane == 0) {
        float vx = 0.f, vy = 0.f, vz = 0.f;
#pragma unroll
        for (int j = 0; j < 8; j++) {
            float wg = e[j] * inv * s_gate[j][h];
            vx = fmaf(wg, s_unit[j][0], vx);
            vy = fmaf(wg, s_unit[j][1], vy);
            vz = fmaf(wg, s_unit[j][2], vz);
        }
        float vn = sqrtf(vx * vx + vy * vy + vz * vz + 1e-8f);
        store2(g_Al0, g_Al1, (size_t)n * ATTKP + 512 + h, vn);
    }
}

// ---------------- H2 extra columns (aa feats through dyntanh2) -> limbs ----------
__global__ void h2extra_kernel(const float* __restrict__ x, const float* __restrict__ alpha2,
                               const float* __restrict__ g2, const float* __restrict__ b2) {
    int t = blockIdx.x * blockDim.x + threadIdx.x;
    if (t >= NN * 20) return;
    int n = t / 20, j = t % 20;
    float a = *alpha2;
    float v = tanhf(a * x[(size_t)n * CC + j]) * g2[512 + j] + b2[512 + j];
    store2(g_Hl0, g_Hl1, (size_t)n * H2KP + 512 + j, v);
}

// ---------------- VQ: 4 nodes per block, no global atomics ----------------
__global__ void vq_kernel(const float* __restrict__ cb, float* __restrict__ out) {
    int grp = threadIdx.x >> 6, t = threadIdx.x & 63;
    int n = blockIdx.x * 4 + grp;
    __shared__ float s_z[4][64];
    __shared__ float s_wsc[4][2];
    __shared__ int s_wbi[4][2];
    __shared__ int s_bi[4];
    s_z[grp][t] = g_Z[(size_t)n * 64 + t];
    __syncthreads();
    float dot = 0.f, cn = 0.f;
    const float* ce = cb + (size_t)t * 64;
#pragma unroll 8
    for (int d = 0; d < 64; d++) {
        float c = ce[d];
        dot = fmaf(s_z[grp][d], c, dot);
        cn = fmaf(c, c, cn);
    }
    float sc = cn - 2.f * dot;
    int bi = t;
    // warp min-reduce with first-index tie-break
#pragma unroll
    for (int o = 16; o; o >>= 1) {
        float osc = __shfl_xor_sync(0xffffffffu, sc, o);
        int obi = __shfl_xor_sync(0xffffffffu, bi, o);
        if (osc < sc || (osc == sc && obi < bi)) { sc = osc; bi = obi; }
    }
    if ((t & 31) == 0) { s_wsc[grp][t >> 5] = sc; s_wbi[grp][t >> 5] = bi; }
    __syncthreads();
    if (t == 0) {
        float s0 = s_wsc[grp][0], s1 = s_wsc[grp][1];
        int b0 = s_wbi[grp][0], b1 = s_wbi[grp][1];
        s_bi[grp] = (s1 < s0 || (s1 == s0 && b1 < b0)) ? b1 : b0;
    }
    __syncthreads();
    int best = s_bi[grp];
    float zq = cb[(size_t)best * 64 + t];
    out[(size_t)n * 64 + t] = zq;
    float df = s_z[grp][t] - zq;
    df = df * df;
#pragma unroll
    for (int o = 16; o; o >>= 1) df += __shfl_xor_sync(0xffffffffu, df, o);
    if ((t & 31) == 0) s_wsc[grp][t >> 5] = df;
    __syncthreads();
    if (t == 0) g_part[n] = s_wsc[grp][0] + s_wsc[grp][1];
}

__global__ void loss_reduce_kernel(float* __restrict__ out) {
    __shared__ double s_s[32];
    int tid = threadIdx.x;
    double s = 0.0;
    for (int i = tid; i < NN; i += 1024) s += (double)g_part[i];
#pragma unroll
    for (int o = 16; o; o >>= 1) s += __shfl_xor_sync(0xffffffffu, s, o);
    if ((tid & 31) == 0) s_s[tid >> 5] = s;
    __syncthreads();
    if (tid == 0) {
        double tot = 0.0;
        for (int i = 0; i < 32; i++) tot += s_s[i];
        out[(size_t)NN * OUTD] = (float)(0.25 * tot / (double)((size_t)NN * OUTD));
    }
}

// ---------------- launch ----------------
extern "C" void kernel_launch(void* const* d_in, const int* in_sizes, int n_in,
                              void* d_out, int out_size) {
    const float *x, *coors, *Wq, *Wk, *Wv, *wg, *Wr1, *br1, *Wr2, *br2, *Wo;
    const float *a1, *g1, *b1, *Wlin, *blin, *a2, *g2, *b2, *Wout, *bout, *cb;
    const int* nbr;

    if (n_in > 5 && in_sizes[5] == 2048) {
        x = (const float*)d_in[0];   coors = (const float*)d_in[1];
        Wq = (const float*)d_in[2];  Wk = (const float*)d_in[3];  Wv = (const float*)d_in[4];
        wg = (const float*)d_in[5];  Wr1 = (const float*)d_in[6]; br1 = (const float*)d_in[7];
        Wr2 = (const float*)d_in[8]; br2 = (const float*)d_in[9]; Wo = (const float*)d_in[10];
        a1 = (const float*)d_in[11]; g1 = (const float*)d_in[12]; b1 = (const float*)d_in[13];
        Wlin = (const float*)d_in[14]; blin = (const float*)d_in[15];
        a2 = (const float*)d_in[16]; g2 = (const float*)d_in[17]; b2 = (const float*)d_in[18];
        Wout = (const float*)d_in[19]; bout = (const float*)d_in[20];
        cb = (const float*)d_in[21]; nbr = (const int*)d_in[22];
    } else {
        x = (const float*)d_in[0];   coors = (const float*)d_in[1];
        nbr = (const int*)d_in[2];
        Wq = (const float*)d_in[3];  Wk = (const float*)d_in[4];  Wv = (const float*)d_in[5];
        wg = (const float*)d_in[6];  Wr1 = (const float*)d_in[7]; br1 = (const float*)d_in[8];
        Wr2 = (const float*)d_in[9]; br2 = (const float*)d_in[10]; Wo = (const float*)d_in[11];
        a1 = (const float*)d_in[12]; g1 = (const float*)d_in[13]; b1 = (const float*)d_in[14];
        Wlin = (const float*)d_in[15]; blin = (const float*)d_in[16];
        a2 = (const float*)d_in[17]; g2 = (const float*)d_in[18]; b2 = (const float*)d_in[19];
        Wout = (const float*)d_in[20]; bout = (const float*)d_in[21];
        cb = (const float*)d_in[22];
    }

    float *pQKV, *pZ;
    cudaGetSymbolAddress((void**)&pQKV, g_QKV);
    cudaGetSymbolAddress((void**)&pZ, g_Z);
    __half *xl0, *xl1, *Al0, *Al1, *Tl0, *Tl1, *Hl0, *Hl1;
    cudaGetSymbolAddress((void**)&xl0, g_xl0); cudaGetSymbolAddress((void**)&xl1, g_xl1);
    cudaGetSymbolAddress((void**)&Al0, g_Al0); cudaGetSymbolAddress((void**)&Al1, g_Al1);
    cudaGetSymbolAddress((void**)&Tl0, g_Tl0); cudaGetSymbolAddress((void**)&Tl1, g_Tl1);
    cudaGetSymbolAddress((void**)&Hl0, g_Hl0); cudaGetSymbolAddress((void**)&Hl1, g_Hl1);
    __half *Bq0, *Bq1, *Bo0, *Bo1, *Bl0, *Bl1, *Bu0, *Bu1;
    cudaGetSymbolAddress((void**)&Bq0, g_Bq0); cudaGetSymbolAddress((void**)&Bq1, g_Bq1);
    cudaGetSymbolAddress((void**)&Bo0, g_Bo0); cudaGetSymbolAddress((void**)&Bo1, g_Bo1);
    cudaGetSymbolAddress((void**)&Bl0, g_Bl0); cudaGetSymbolAddress((void**)&Bl1, g_Bl1);
    cudaGetSymbolAddress((void**)&Bu0, g_Bu0); cudaGetSymbolAddress((void**)&Bu1, g_Bu1);

    float* out = (float*)d_out;

    constexpr int SM128 = (2 * 128 + 2 * 128) * 72 * 2;  // 73728
    constexpr int SM64 = (2 * 128 + 2 * 64) * 72 * 2;    // 55296
    cudaFuncSetAttribute(mmagemm<128, 0>, cudaFuncAttributeMaxDynamicSharedMemorySize, SM128);
    cudaFuncSetAttribute(mmagemm<128, 1>, cudaFuncAttributeMaxDynamicSharedMemorySize, SM128);
    cudaFuncSetAttribute(mmagemm<128, 2>, cudaFuncAttributeMaxDynamicSharedMemorySize, SM128);
    cudaFuncSetAttribute(mmagemm<64, 3>, cudaFuncAttributeMaxDynamicSharedMemorySize, SM64);

    // conversions: x and weights -> fp16 limbs
    convA_kernel<<<(NN * CC + 255) / 256, 256>>>(x, xl0, xl1, NN * CC);
    convBqkv_kernel<<<(QKVW * CC + 255) / 256, 256>>>(Wq, Wk, Wv, Bq0, Bq1);
    convB_kernel<<<(CC * 520 + 255) / 256, 256>>>(Wo, Bo0, Bo1, 520, CC, ATTKP);
    convB_kernel<<<(HIDD * CC + 255) / 256, 256>>>(Wlin, Bl0, Bl1, CC, HIDD, CC);
    convB_kernel<<<(OUTD * 532 + 255) / 256, 256>>>(Wout, Bu0, Bu1, 532, OUTD, H2KP);

    // QKV = x @ [Wq|Wk|Wv]  -> fp32
    mmagemm<128, 0><<<dim3(QKVW / 128, NN / 128), 256, SM128>>>(
        xl0, xl1, Bq0, Bq1, CC,
        pQKV, QKVW, nullptr, nullptr, 0,
        nullptr, nullptr, 0, nullptr, nullptr, nullptr);

    gate_kernel<<<NN / 8, 256>>>(x, wg);
    attn_kernel<<<NN, 256>>>(coors, nbr, Wr1, br1, Wr2, br2);

    // T = dyntanh(x + Att@Wo) -> limbs
    mmagemm<128, 1><<<dim3(CC / 128, NN / 128), 256, SM128>>>(
        Al0, Al1, Bo0, Bo1, ATTKP,
        nullptr, 0, Tl0, Tl1, CC,
        nullptr, x, CC, a1, g1, b1);

    // H2[:, :512] = dyntanh2(gelu(T@Wlin + blin)) -> limbs
    mmagemm<128, 2><<<dim3(HIDD / 128, NN / 128), 256, SM128>>>(
        Tl0, Tl1, Bl0, Bl1, CC,
        nullptr, 0, Hl0, Hl1, H2KP,
        blin, nullptr, 0, a2, g2, b2);
    h2extra_kernel<<<(NN * 20 + 255) / 256, 256>>>(x, a2, g2, b2);

    // Z = tanh(gelu(H2@Wout + bout)) -> fp32
    mmagemm<64, 3><<<dim3(1, NN / 128), 256, SM64>>>(
        Hl0, Hl1, Bu0, Bu1, H2KP,
        pZ, OUTD, nullptr, nullptr, 0,
        bout, nullptr, 0, nullptr, nullptr, nullptr);

    vq_kernel<<<NN / 4, 256>>>(cb, out);
    if (out_size > NN * OUTD) loss_reduce_kernel<<<1, 1024>>>(out);
}

// round 8
// speedup vs baseline: 1.0099x; 1.0099x over previous
#include <cuda_runtime.h>
#include <cuda_fp16.h>
#include <math.h>
#include <cstdint>

#define NN 16384
#define CC 256
#define HH 8
#define HD 512
#define QKVW 1536
#define HIDD 512
#define OUTD 64
#define H2D 532
#define ATTKP 576   // 520 padded to 64-multiple
#define H2KP 576    // 532 padded

// ---------------- scratch (static device arrays; no allocation) ----------------
__device__ float g_QKV[NN * QKVW];          // fp32 Q|K|V for attention
__device__ float g_G[NN * HH];
__device__ float g_Z[NN * OUTD];
__device__ float g_part[NN];                // per-node vq loss partials

// activation fp16 limbs (zero-init pads stay zero forever)
__device__ __half g_xl0[NN * CC], g_xl1[NN * CC];
__device__ __half g_Al0[NN * ATTKP], g_Al1[NN * ATTKP];
__device__ __half g_Tl0[NN * CC], g_Tl1[NN * CC];
__device__ __half g_Hl0[NN * H2KP], g_Hl1[NN * H2KP];

// weight fp16 limbs, [N, Kp] K-major
__device__ __half g_Bq0[QKVW * CC], g_Bq1[QKVW * CC];
__device__ __half g_Bo0[CC * ATTKP], g_Bo1[CC * ATTKP];
__device__ __half g_Bl0[HIDD * CC], g_Bl1[HIDD * CC];
__device__ __half g_Bu0[OUTD * H2KP], g_Bu1[OUTD * H2KP];

// ---------------- helpers ----------------
__device__ __forceinline__ float gelu_tanh(float x) {
    float x3 = x * x * x;
    return 0.5f * x * (1.0f + tanhf(0.7978845608028654f * (x + 0.044715f * x3)));
}

__device__ __forceinline__ void store2(__half* p0, __half* p1, size_t off, float v) {
    __half h0 = __float2half_rn(v);
    __half h1 = __float2half_rn(v - __half2float(h0));
    p0[off] = h0;
    p1[off] = h1;
}

__device__ __forceinline__ uint32_t smem_u32(const void* p) {
    uint32_t a;
    asm("{ .reg .u64 t; cvta.to.shared.u64 t, %1; cvt.u32.u64 %0, t; }" : "=r"(a) : "l"(p));
    return a;
}

__device__ __forceinline__ void ldsm4(uint32_t* r, uint32_t addr) {
    asm volatile("ldmatrix.sync.aligned.m8n8.x4.shared.b16 {%0,%1,%2,%3}, [%4];"
                 : "=r"(r[0]), "=r"(r[1]), "=r"(r[2]), "=r"(r[3]) : "r"(addr));
}

__device__ __forceinline__ void mma16816(float* c, const uint32_t* a, const uint32_t* b) {
    asm volatile(
        "mma.sync.aligned.m16n8k16.row.col.f32.f16.f16.f32 "
        "{%0,%1,%2,%3}, {%4,%5,%6,%7}, {%8,%9}, {%0,%1,%2,%3};"
        : "+f"(c[0]), "+f"(c[1]), "+f"(c[2]), "+f"(c[3])
        : "r"(a[0]), "r"(a[1]), "r"(a[2]), "r"(a[3]), "r"(b[0]), "r"(b[1]));
}

__device__ __forceinline__ void cpasync16(uint32_t saddr, const void* gptr) {
    asm volatile("cp.async.cg.shared.global [%0], [%1], 16;"
                 :: "r"(saddr), "l"(gptr) : "memory");
}

// ============== mma.sync fp16 2-limb 3-pass GEMM, cp.async 2-stage pipeline ======
// A limbs: [M, Kp] row-major fp16.  B limbs: [N, Kp] K-major fp16.
// CTA tile 128 x NT, 8 warps (2m x 4n). Pass-major item sequence (3 passes x nch).
// EPI: 0=fp32 plain, 1=resid+dyntanh->limbs, 2=gelu(bias)+dyntanh->limbs,
//      3=tanh(gelu(bias))->fp32
template <int NT, int EPI>
__global__ __launch_bounds__(256) void mmagemm(
        const __half* __restrict__ A0, const __half* __restrict__ A1,
        const __half* __restrict__ B0, const __half* __restrict__ B1,
        int Kp,
        float* __restrict__ outF, int ldoF,
        __half* __restrict__ O0, __half* __restrict__ O1, int ldoL,
        const float* __restrict__ bias, const float* __restrict__ resid, int ldr,
        const float* __restrict__ alpha_p,
        const float* __restrict__ gv, const float* __restrict__ bv) {
    extern __shared__ __half sm[];
    constexpr int NF = NT / 32;          // n-frags per warp (8 cols each)
    constexpr int ROWB = 144;            // bytes per smem row (72 halves)
    constexpr int ABYTES = 128 * ROWB;
    constexpr int STAGE = (128 + NT) * ROWB;

    uint32_t sbase = smem_u32(sm);
    int tid = threadIdx.x, lane = tid & 31, wid = tid >> 5;
    int wm = wid & 1, wn = wid >> 1;
    int bm = blockIdx.y * 128, bn = blockIdx.x * NT;
    int nch = Kp >> 6;
    int nit = 3 * nch;

    float acc[4][NF][4];
#pragma unroll
    for (int i = 0; i < 4; i++)
#pragma unroll
        for (int j = 0; j < NF; j++)
#pragma unroll
            for (int c = 0; c < 4; c++) acc[i][j][c] = 0.f;

    auto issue = [&](int it, int s) {
        int t = it / nch, c = it - (it / nch) * nch;
        // passes: (A0,B0), (A0,B1), (A1,B0)
        const __half* Ab = (t == 2) ? A1 : A0;
        const __half* Bb = (t == 1) ? B1 : B0;
        uint32_t abase = sbase + (uint32_t)s * STAGE;
#pragma unroll
        for (int q = 0; q < 4; q++) {
            int idx = tid + q * 256;
            int row = idx >> 3, cg = idx & 7;
            cpasync16(abase + row * ROWB + cg * 16,
                      Ab + (size_t)(bm + row) * Kp + c * 64 + cg * 8);
        }
        uint32_t bbase = abase + ABYTES;
#pragma unroll
        for (int q = 0; q < NF; q++) {
            int idx = tid + q * 256;
            int row = idx >> 3, cg = idx & 7;
            cpasync16(bbase + row * ROWB + cg * 16,
                      Bb + (size_t)(bn + row) * Kp + c * 64 + cg * 8);
        }
        asm volatile("cp.async.commit_group;" ::: "memory");
    };

    issue(0, 0);

#pragma unroll 1
    for (int it = 0; it < nit; it++) {
        int s = it & 1;
        if (it + 1 < nit) {
            issue(it + 1, s ^ 1);
            asm volatile("cp.async.wait_group 1;" ::: "memory");
        } else {
            asm volatile("cp.async.wait_group 0;" ::: "memory");
        }
        __syncthreads();

        uint32_t abase = sbase + (uint32_t)s * STAGE;
        uint32_t bbase = abase + ABYTES;
#pragma unroll
        for (int kk = 0; kk < 4; kk++) {
            int k = kk * 16;
            int arow = wm * 64 + (lane & 15);
            int acol = k + (lane >> 4) * 8;
            int g = lane >> 3;
            int nr = wn * (NT / 4) + ((g >> 1) << 3) + (lane & 7);
            int kc = k + (g & 1) * 8;

            uint32_t a[4][4];
#pragma unroll
            for (int i = 0; i < 4; i++)
                ldsm4(a[i], abase + (arow + i * 16) * ROWB + acol * 2);
            uint32_t b[NF][2];
#pragma unroll
            for (int jj = 0; jj < NF / 2; jj++) {
                uint32_t tmp[4];
                ldsm4(tmp, bbase + (nr + jj * 16) * ROWB + kc * 2);
                b[2 * jj][0] = tmp[0]; b[2 * jj][1] = tmp[1];
                b[2 * jj + 1][0] = tmp[2]; b[2 * jj + 1][1] = tmp[3];
            }
#pragma unroll
            for (int i = 0; i < 4; i++)
#pragma unroll
                for (int j = 0; j < NF; j++) mma16816(acc[i][j], a[i], b[j]);
        }
        __syncthreads();
    }

    // ---------------- epilogue ----------------
    float alpha = (EPI == 1 || EPI == 2) ? *alpha_p : 0.f;
    int gid = lane >> 2, tig = lane & 3;
#pragma unroll
    for (int i = 0; i < 4; i++) {
#pragma unroll
        for (int j = 0; j < NF; j++) {
#pragma unroll
            for (int cc = 0; cc < 4; cc++) {
                int m = bm + wm * 64 + i * 16 + gid + (cc >> 1) * 8;
                int ncol = bn + wn * (NT / 4) + j * 8 + tig * 2 + (cc & 1);
                float v = acc[i][j][cc];
                if (EPI == 0) {
                    outF[(size_t)m * ldoF + ncol] = v;
                } else if (EPI == 1) {
                    v += resid[(size_t)m * ldr + ncol];
                    v = tanhf(alpha * v) * gv[ncol] + bv[ncol];
                    store2(O0, O1, (size_t)m * ldoL + ncol, v);
                } else if (EPI == 2) {
                    v = gelu_tanh(v + bias[ncol]);
                    v = tanhf(alpha * v) * gv[ncol] + bv[ncol];
                    store2(O0, O1, (size_t)m * ldoL + ncol, v);
                } else {
                    v = tanhf(gelu_tanh(v + bias[ncol]));
                    outF[(size_t)m * ldoF + ncol] = v;
                }
            }
        }
    }
}

// ---------------- conversions ----------------
__global__ void convA_kernel(const float* __restrict__ src, __half* d0, __half* d1, int n) {
    int t = blockIdx.x * blockDim.x + threadIdx.x;
    if (t >= n) return;
    store2(d0, d1, t, src[t]);
}

__global__ void convB_kernel(const float* __restrict__ src, __half* d0, __half* d1,
                             int K, int N, int Kp) {
    int t = blockIdx.x * blockDim.x + threadIdx.x;
    if (t >= N * K) return;
    int n = t / K, k = t - n * K;
    store2(d0, d1, (size_t)n * Kp + k, src[(size_t)k * N + n]);
}

__global__ void convBqkv_kernel(const float* __restrict__ Wq, const float* __restrict__ Wk,
                                const float* __restrict__ Wv, __half* d0, __half* d1) {
    int t = blockIdx.x * blockDim.x + threadIdx.x;
    if (t >= QKVW * CC) return;
    int n = t >> 8, k = t & 255;
    const float* s = (n < 512) ? Wq : ((n < 1024) ? Wk : Wv);
    int col = n & 511;
    store2(d0, d1, (size_t)n * CC + k, s[(size_t)k * 512 + col]);
}

// ---------------- gate projection: warp per node ----------------
__global__ void gate_kernel(const float* __restrict__ x, const float* __restrict__ wg) {
    int wid = threadIdx.x >> 5, lane = threadIdx.x & 31;
    int n = blockIdx.x * 8 + wid;
    if (n >= NN) return;
    const float* xr = x + (size_t)n * CC;
    float4 v0 = *(const float4*)(xr + lane * 8);
    float4 v1 = *(const float4*)(xr + lane * 8 + 4);
    float xv[8] = {v0.x, v0.y, v0.z, v0.w, v1.x, v1.y, v1.z, v1.w};
#pragma unroll
    for (int h = 0; h < 8; h++) {
        float p = 0.f;
#pragma unroll
        for (int i = 0; i < 8; i++) p = fmaf(xv[i], wg[(lane * 8 + i) * 8 + h], p);
#pragma unroll
        for (int o = 16; o; o >>= 1) p += __shfl_xor_sync(0xffffffffu, p, o);
        if (lane == 0) g_G[(size_t)n * 8 + h] = p;
    }
}

// ---------------- attention: block per node, warp per head; writes Att limbs ------
__global__ void attn_kernel(const float* __restrict__ coors, const int* __restrict__ nbr,
                            const float* __restrict__ Wr1, const float* __restrict__ br1,
                            const float* __restrict__ Wr2, const float* __restrict__ br2) {
    int n = blockIdx.x;
    int tid = threadIdx.x;
    __shared__ int s_nbr[8];
    __shared__ float s_dist[8];
    __shared__ float s_unit[8][3];
    __shared__ float s_rad[8][8];
    __shared__ float s_gate[8][8];

    if (tid < 8) s_nbr[tid] = nbr[(size_t)n * 8 + tid];
    __syncthreads();
    if (tid < 8) {
        int j = tid;
        float cx = coors[(size_t)n * 3], cy = coors[(size_t)n * 3 + 1], cz = coors[(size_t)n * 3 + 2];
        int mm = s_nbr[j];
        float rx = coors[(size_t)mm * 3] - cx;
        float ry = coors[(size_t)mm * 3 + 1] - cy;
        float rz = coors[(size_t)mm * 3 + 2] - cz;
        float d = sqrtf(rx * rx + ry * ry + rz * rz + 1e-8f);
        s_dist[j] = d;
        s_unit[j][0] = rx / d;
        s_unit[j][1] = ry / d;
        s_unit[j][2] = rz / d;
    }
    __syncthreads();
    if (tid < 64) {
        int j = tid >> 3, h = tid & 7;
        float d = s_dist[j];
        float acc = br2[h];
#pragma unroll
        for (int i = 0; i < 16; i++)
            acc = fmaf(gelu_tanh(d * Wr1[i] + br1[i]), Wr2[i * 8 + h], acc);
        s_rad[j][h] = acc;
        s_gate[j][h] = g_G[(size_t)s_nbr[j] * HH + h];
    }
    __syncthreads();

    int w = tid >> 5, lane = tid & 31;
    int h = w;
    const float* qr = g_QKV + (size_t)n * QKVW + h * 64;
    float q0 = qr[lane * 2], q1 = qr[lane * 2 + 1];
    float logit[8];
#pragma unroll
    for (int j = 0; j < 8; j++) {
        const float* kr = g_QKV + (size_t)s_nbr[j] * QKVW + 512 + h * 64;
        float p = q0 * kr[lane * 2] + q1 * kr[lane * 2 + 1];
#pragma unroll
        for (int o = 16; o; o >>= 1) p += __shfl_xor_sync(0xffffffffu, p, o);
        p = p * 0.125f + s_rad[j][h];
        logit[j] = (s_dist[j] <= 10.0f) ? p : -1e9f;
    }
    float mx = logit[0];
#pragma unroll
    for (int j = 1; j < 8; j++) mx = fmaxf(mx, logit[j]);
    float e[8];
    float se = 0.f;
#pragma unroll
    for (int j = 0; j < 8; j++) { e[j] = expf(logit[j] - mx); se += e[j]; }
    float inv = 1.f / se;
    float a0 = 0.f, a1 = 0.f;
#pragma unroll
    for (int j = 0; j < 8; j++) {
        float at = e[j] * inv;
        const float* vr = g_QKV + (size_t)s_nbr[j] * QKVW + 1024 + h * 64;
        a0 = fmaf(at, vr[lane * 2], a0);
        a1 = fmaf(at, vr[lane * 2 + 1], a1);
    }
    size_t base = (size_t)n * ATTKP + h * 64 + lane * 2;
    store2(g_Al0, g_Al1, base, a0);
    store2(g_Al0, g_Al1, base + 1, a1);
    if (lane == 0) {
        float vx = 0.f, vy = 0.f, vz = 0.f;
#pragma unroll
        for (int j = 0; j < 8; j++) {
            float wg = e[j] * inv * s_gate[j][h];
            vx = fmaf(wg, s_unit[j][0], vx);
            vy = fmaf(wg, s_unit[j][1], vy);
            vz = fmaf(wg, s_unit[j][2], vz);
        }
        float vn = sqrtf(vx * vx + vy * vy + vz * vz + 1e-8f);
        store2(g_Al0, g_Al1, (size_t)n * ATTKP + 512 + h, vn);
    }
}

// ---------------- H2 extra columns (aa feats through dyntanh2) -> limbs ----------
__global__ void h2extra_kernel(const float* __restrict__ x, const float* __restrict__ alpha2,
                               const float* __restrict__ g2, const float* __restrict__ b2) {
    int t = blockIdx.x * blockDim.x + threadIdx.x;
    if (t >= NN * 20) return;
    int n = t / 20, j = t % 20;
    float a = *alpha2;
    float v = tanhf(a * x[(size_t)n * CC + j]) * g2[512 + j] + b2[512 + j];
    store2(g_Hl0, g_Hl1, (size_t)n * H2KP + 512 + j, v);
}

// ---------------- VQ: 4 nodes per block, no global atomics ----------------
__global__ void vq_kernel(const float* __restrict__ cb, float* __restrict__ out) {
    int grp = threadIdx.x >> 6, t = threadIdx.x & 63;
    int n = blockIdx.x * 4 + grp;
    __shared__ float s_z[4][64];
    __shared__ float s_wsc[4][2];
    __shared__ int s_wbi[4][2];
    __shared__ int s_bi[4];
    s_z[grp][t] = g_Z[(size_t)n * 64 + t];
    __syncthreads();
    float dot = 0.f, cn = 0.f;
    const float* ce = cb + (size_t)t * 64;
#pragma unroll 8
    for (int d = 0; d < 64; d++) {
        float c = ce[d];
        dot = fmaf(s_z[grp][d], c, dot);
        cn = fmaf(c, c, cn);
    }
    float sc = cn - 2.f * dot;
    int bi = t;
#pragma unroll
    for (int o = 16; o; o >>= 1) {
        float osc = __shfl_xor_sync(0xffffffffu, sc, o);
        int obi = __shfl_xor_sync(0xffffffffu, bi, o);
        if (osc < sc || (osc == sc && obi < bi)) { sc = osc; bi = obi; }
    }
    if ((t & 31) == 0) { s_wsc[grp][t >> 5] = sc; s_wbi[grp][t >> 5] = bi; }
    __syncthreads();
    if (t == 0) {
        float s0 = s_wsc[grp][0], s1 = s_wsc[grp][1];
        int b0 = s_wbi[grp][0], b1 = s_wbi[grp][1];
        s_bi[grp] = (s1 < s0 || (s1 == s0 && b1 < b0)) ? b1 : b0;
    }
    __syncthreads();
    int best = s_bi[grp];
    float zq = cb[(size_t)best * 64 + t];
    out[(size_t)n * 64 + t] = zq;
    float df = s_z[grp][t] - zq;
    df = df * df;
#pragma unroll
    for (int o = 16; o; o >>= 1) df += __shfl_xor_sync(0xffffffffu, df, o);
    if ((t & 31) == 0) s_wsc[grp][t >> 5] = df;
    __syncthreads();
    if (t == 0) g_part[n] = s_wsc[grp][0] + s_wsc[grp][1];
}

__global__ void loss_reduce_kernel(float* __restrict__ out) {
    __shared__ double s_s[32];
    int tid = threadIdx.x;
    double s = 0.0;
    for (int i = tid; i < NN; i += 1024) s += (double)g_part[i];
#pragma unroll
    for (int o = 16; o; o >>= 1) s += __shfl_xor_sync(0xffffffffu, s, o);
    if ((tid & 31) == 0) s_s[tid >> 5] = s;
    __syncthreads();
    if (tid == 0) {
        double tot = 0.0;
        for (int i = 0; i < 32; i++) tot += s_s[i];
        out[(size_t)NN * OUTD] = (float)(0.25 * tot / (double)((size_t)NN * OUTD));
    }
}

// ---------------- launch ----------------
extern "C" void kernel_launch(void* const* d_in, const int* in_sizes, int n_in,
                              void* d_out, int out_size) {
    const float *x, *coors, *Wq, *Wk, *Wv, *wg, *Wr1, *br1, *Wr2, *br2, *Wo;
    const float *a1, *g1, *b1, *Wlin, *blin, *a2, *g2, *b2, *Wout, *bout, *cb;
    const int* nbr;

    if (n_in > 5 && in_sizes[5] == 2048) {
        x = (const float*)d_in[0];   coors = (const float*)d_in[1];
        Wq = (const float*)d_in[2];  Wk = (const float*)d_in[3];  Wv = (const float*)d_in[4];
        wg = (const float*)d_in[5];  Wr1 = (const float*)d_in[6]; br1 = (const float*)d_in[7];
        Wr2 = (const float*)d_in[8]; br2 = (const float*)d_in[9]; Wo = (const float*)d_in[10];
        a1 = (const float*)d_in[11]; g1 = (const float*)d_in[12]; b1 = (const float*)d_in[13];
        Wlin = (const float*)d_in[14]; blin = (const float*)d_in[15];
        a2 = (const float*)d_in[16]; g2 = (const float*)d_in[17]; b2 = (const float*)d_in[18];
        Wout = (const float*)d_in[19]; bout = (const float*)d_in[20];
        cb = (const float*)d_in[21]; nbr = (const int*)d_in[22];
    } else {
        x = (const float*)d_in[0];   coors = (const float*)d_in[1];
        nbr = (const int*)d_in[2];
        Wq = (const float*)d_in[3];  Wk = (const float*)d_in[4];  Wv = (const float*)d_in[5];
        wg = (const float*)d_in[6];  Wr1 = (const float*)d_in[7]; br1 = (const float*)d_in[8];
        Wr2 = (const float*)d_in[9]; br2 = (const float*)d_in[10]; Wo = (const float*)d_in[11];
        a1 = (const float*)d_in[12]; g1 = (const float*)d_in[13]; b1 = (const float*)d_in[14];
        Wlin = (const float*)d_in[15]; blin = (const float*)d_in[16];
        a2 = (const float*)d_in[17]; g2 = (const float*)d_in[18]; b2 = (const float*)d_in[19];
        Wout = (const float*)d_in[20]; bout = (const float*)d_in[21];
        cb = (const float*)d_in[22];
    }

    float *pQKV, *pZ;
    cudaGetSymbolAddress((void**)&pQKV, g_QKV);
    cudaGetSymbolAddress((void**)&pZ, g_Z);
    __half *xl0, *xl1, *Al0, *Al1, *Tl0, *Tl1, *Hl0, *Hl1;
    cudaGetSymbolAddress((void**)&xl0, g_xl0); cudaGetSymbolAddress((void**)&xl1, g_xl1);
    cudaGetSymbolAddress((void**)&Al0, g_Al0); cudaGetSymbolAddress((void**)&Al1, g_Al1);
    cudaGetSymbolAddress((void**)&Tl0, g_Tl0); cudaGetSymbolAddress((void**)&Tl1, g_Tl1);
    cudaGetSymbolAddress((void**)&Hl0, g_Hl0); cudaGetSymbolAddress((void**)&Hl1, g_Hl1);
    __half *Bq0, *Bq1, *Bo0, *Bo1, *Bl0, *Bl1, *Bu0, *Bu1;
    cudaGetSymbolAddress((void**)&Bq0, g_Bq0); cudaGetSymbolAddress((void**)&Bq1, g_Bq1);
    cudaGetSymbolAddress((void**)&Bo0, g_Bo0); cudaGetSymbolAddress((void**)&Bo1, g_Bo1);
    cudaGetSymbolAddress((void**)&Bl0, g_Bl0); cudaGetSymbolAddress((void**)&Bl1, g_Bl1);
    cudaGetSymbolAddress((void**)&Bu0, g_Bu0); cudaGetSymbolAddress((void**)&Bu1, g_Bu1);

    float* out = (float*)d_out;

    constexpr int SM128 = 2 * (128 + 128) * 144;  // 73728
    constexpr int SM64 = 2 * (128 + 64) * 144;    // 55296
    cudaFuncSetAttribute(mmagemm<128, 0>, cudaFuncAttributeMaxDynamicSharedMemorySize, SM128);
    cudaFuncSetAttribute(mmagemm<128, 1>, cudaFuncAttributeMaxDynamicSharedMemorySize, SM128);
    cudaFuncSetAttribute(mmagemm<128, 2>, cudaFuncAttributeMaxDynamicSharedMemorySize, SM128);
    cudaFuncSetAttribute(mmagemm<64, 3>, cudaFuncAttributeMaxDynamicSharedMemorySize, SM64);

    // launch order puts mmagemm<128,0> in the ncu capture slot (#4)
    convA_kernel<<<(NN * CC + 255) / 256, 256>>>(x, xl0, xl1, NN * CC);          // 1
    convBqkv_kernel<<<(QKVW * CC + 255) / 256, 256>>>(Wq, Wk, Wv, Bq0, Bq1);     // 2
    gate_kernel<<<NN / 8, 256>>>(x, wg);                                         // 3

    // QKV = x @ [Wq|Wk|Wv]  -> fp32                                             // 4
    mmagemm<128, 0><<<dim3(QKVW / 128, NN / 128), 256, SM128>>>(
        xl0, xl1, Bq0, Bq1, CC,
        pQKV, QKVW, nullptr, nullptr, 0,
        nullptr, nullptr, 0, nullptr, nullptr, nullptr);

    convB_kernel<<<(CC * 520 + 255) / 256, 256>>>(Wo, Bo0, Bo1, 520, CC, ATTKP); // 5
    attn_kernel<<<NN, 256>>>(coors, nbr, Wr1, br1, Wr2, br2);                    // 6

    // T = dyntanh(x + Att@Wo) -> limbs
    mmagemm<128, 1><<<dim3(CC / 128, NN / 128), 256, SM128>>>(
        Al0, Al1, Bo0, Bo1, ATTKP,
        nullptr, 0, Tl0, Tl1, CC,
        nullptr, x, CC, a1, g1, b1);

    convB_kernel<<<(HIDD * CC + 255) / 256, 256>>>(Wlin, Bl0, Bl1, CC, HIDD, CC);

    // H2[:, :512] = dyntanh2(gelu(T@Wlin + blin)) -> limbs
    mmagemm<128, 2><<<dim3(HIDD / 128, NN / 128), 256, SM128>>>(
        Tl0, Tl1, Bl0, Bl1, CC,
        nullptr, 0, Hl0, Hl1, H2KP,
        blin, nullptr, 0, a2, g2, b2);
    h2extra_kernel<<<(NN * 20 + 255) / 256, 256>>>(x, a2, g2, b2);
    convB_kernel<<<(OUTD * 532 + 255) / 256, 256>>>(Wout, Bu0, Bu1, 532, OUTD, H2KP);

    // Z = tanh(gelu(H2@Wout + bout)) -> fp32
    mmagemm<64, 3><<<dim3(1, NN / 128), 256, SM64>>>(
        Hl0, Hl1, Bu0, Bu1, H2KP,
        pZ, OUTD, nullptr, nullptr, 0,
        bout, nullptr, 0, nullptr, nullptr, nullptr);

    vq_kernel<<<NN / 4, 256>>>(cb, out);
    if (out_size > NN * OUTD) loss_reduce_kernel<<<1, 1024>>>(out);
}